// round 5
// baseline (speedup 1.0000x reference)
#include <cuda_runtime.h>
#include <cstdint>

#define E_      8
#define D_      512
#define TMAX    32768
#define MAXTILES 264

// ---------------- scratch (allocation-free __device__ globals) ----------------
__device__ int g_counts[E_];
__device__ int g_offsets[E_];
__device__ int g_cursor[E_];
__device__ int g_bucket[TMAX];
__device__ int g_tile_e[MAXTILES];
__device__ int g_tile_m[MAXTILES];
__device__ int g_num_tiles;

__device__ __align__(16) int8_t g_X1[(size_t)TMAX * D_];
__device__ __align__(16) int8_t g_X0[(size_t)TMAX * D_];
__device__ __align__(16) int8_t g_W1[(size_t)E_ * D_ * D_];
__device__ __align__(16) int8_t g_W0[(size_t)E_ * D_ * D_];
__device__ float g_sx[TMAX];
__device__ float g_sw[E_ * D_];

// ---------------- helpers ----------------
__device__ __forceinline__ uint32_t smem_u32(const void* p) {
    uint32_t a;
    asm("{ .reg .u64 t; cvta.to.shared.u64 t, %1; cvt.u32.u64 %0, t; }" : "=r"(a) : "l"(p));
    return a;
}

#define CP16(d, s) asm volatile("cp.async.cg.shared.global [%0], [%1], 16;" :: "r"(d), "l"(s) : "memory")

#define LDSM4(r, a)                                                                  \
    asm volatile("ldmatrix.sync.aligned.m8n8.x4.shared.b16 {%0,%1,%2,%3}, [%4];"     \
        : "=r"((r)[0]), "=r"((r)[1]), "=r"((r)[2]), "=r"((r)[3]) : "r"(a))

// int8 mma: D/C int32, A 4 regs (16x32 s8), B 2 regs (32x8 s8)
#define IMMA(c, a, b0, b1)                                                           \
    asm volatile("mma.sync.aligned.m16n8k32.row.col.s32.s8.s8.s32 "                  \
        "{%0,%1,%2,%3},{%4,%5,%6,%7},{%8,%9},{%0,%1,%2,%3};"                         \
        : "+r"((c)[0]), "+r"((c)[1]), "+r"((c)[2]), "+r"((c)[3])                     \
        : "r"((a)[0]), "r"((a)[1]), "r"((a)[2]), "r"((a)[3]),                        \
          "r"(b0), "r"(b1))

// ---------------- bucketing ----------------
__global__ void k_zero() {
    int i = threadIdx.x;
    if (i < E_) { g_counts[i] = 0; g_cursor[i] = 0; }
}

__global__ void k_count(const int* __restrict__ p, int T) {
    __shared__ int s[E_];
    if (threadIdx.x < E_) s[threadIdx.x] = 0;
    __syncthreads();
    int t = blockIdx.x * blockDim.x + threadIdx.x;
    if (t < T) atomicAdd(&s[p[t]], 1);
    __syncthreads();
    if (threadIdx.x < E_ && s[threadIdx.x]) atomicAdd(&g_counts[threadIdx.x], s[threadIdx.x]);
}

__global__ void k_prefix() {
    if (threadIdx.x == 0) {
        int acc = 0;
        for (int e = 0; e < E_; e++) { g_offsets[e] = acc; acc += g_counts[e]; }
        int nt = 0;
        for (int e = 0; e < E_; e++) {
            int mt = (g_counts[e] + 127) >> 7;
            for (int m = 0; m < mt; m++) { g_tile_e[nt] = e; g_tile_m[nt] = m; nt++; }
        }
        g_num_tiles = nt;
    }
}

__global__ void k_scatter(const int* __restrict__ p, int T) {
    __shared__ int s_cnt[E_], s_base[E_];
    if (threadIdx.x < E_) s_cnt[threadIdx.x] = 0;
    __syncthreads();
    int t = blockIdx.x * blockDim.x + threadIdx.x;
    int e = 0, rank = 0;
    if (t < T) { e = p[t]; rank = atomicAdd(&s_cnt[e], 1); }
    __syncthreads();
    if (threadIdx.x < E_ && s_cnt[threadIdx.x])
        s_base[threadIdx.x] = atomicAdd(&g_cursor[threadIdx.x], s_cnt[threadIdx.x]);
    __syncthreads();
    if (t < T) g_bucket[g_offsets[e] + s_base[e] + rank] = t;
}

// ---------------- per-row 2-limb int8 quantization ----------------
// One warp per 512-float row. x = sx*(256*X1 + X0), divisor 32512 = 127*256.
__device__ __forceinline__ void quant_row(const float* __restrict__ src,
                                          int8_t* __restrict__ hi,
                                          int8_t* __restrict__ lo,
                                          float* __restrict__ scale,
                                          int row, int lane) {
    union { float4 q[4]; float f[16]; } u;
    const float4* s = (const float4*)(src + (size_t)row * D_ + lane * 16);
    float mx = 0.f;
    #pragma unroll
    for (int j = 0; j < 4; j++) {
        u.q[j] = s[j];
        mx = fmaxf(mx, fmaxf(fmaxf(fabsf(u.q[j].x), fabsf(u.q[j].y)),
                             fmaxf(fabsf(u.q[j].z), fabsf(u.q[j].w))));
    }
    #pragma unroll
    for (int o = 16; o > 0; o >>= 1)
        mx = fmaxf(mx, __shfl_xor_sync(0xFFFFFFFF, mx, o));
    mx = fmaxf(mx, 1e-30f);
    const float inv = 32512.0f / mx;

    union { char c[16]; int4 v; } hb, lb;
    #pragma unroll
    for (int i = 0; i < 16; i++) {
        int X = __float2int_rn(u.f[i] * inv);
        int X1 = (X + 128) >> 8;
        hb.c[i] = (char)X1;
        lb.c[i] = (char)(X - (X1 << 8));
    }
    ((int4*)(hi + (size_t)row * D_))[lane] = hb.v;
    ((int4*)(lo + (size_t)row * D_))[lane] = lb.v;
    if (lane == 0) scale[row] = mx * (1.0f / 32512.0f);
}

__global__ void k_quant_x(const float* __restrict__ x) {
    int row = blockIdx.x * 8 + (threadIdx.x >> 5);
    quant_row(x, g_X1, g_X0, g_sx, row, threadIdx.x & 31);
}

__global__ void k_quant_w(const float* __restrict__ W) {
    int row = blockIdx.x * 8 + (threadIdx.x >> 5);
    quant_row(W, g_W1, g_W0, g_sw, row, threadIdx.x & 31);
}

// ---------------- grouped GEMM: IMMA 3-limb int8 ----------------
// CTA 128(M) x 128(N), K=512 in 16 chunks of 32 int8. 512 threads, 16 warps,
// warp tile 32x32. smem tile = 128 rows x 32 B, chunk swizzle c' = c ^ ((r>>2)&1).
#define OFF_A1   0
#define OFF_A0   4096
#define OFF_W1   8192
#define OFF_W0   12288
#define STG      16384
#define NST      4
#define SMEM_GEMM (1024 + NST * STG)

__global__ void __launch_bounds__(512, 1)
k_gemm(const float* __restrict__ bias, float* __restrict__ out) {
    extern __shared__ unsigned char smem[];
    const int ti = blockIdx.y;
    if (ti >= g_num_tiles) return;
    const int nt    = blockIdx.x;
    const int e     = g_tile_e[ti];
    const int mtile = g_tile_m[ti];
    const int count = g_counts[e];
    const int base  = g_offsets[e];

    int* rows = (int*)smem;
    const int tid = threadIdx.x, lane = tid & 31, wid = tid >> 5;

    if (tid < 128) {
        int m = mtile * 128 + tid;
        rows[tid] = (m < count) ? g_bucket[base + m] : -1;
    }
    __syncthreads();

    // ---- loader: 512 threads -> 4 tiles x 128 rows, 32B/row ----
    const int lt = tid >> 7;          // tile: 0=A1 1=A0 2=W1 3=W0
    const int lr = tid & 127;
    const int8_t* lsrc;
    if (lt < 2) {
        int tok = rows[lr]; if (tok < 0) tok = 0;
        lsrc = (lt == 0 ? g_X1 : g_X0) + (size_t)tok * D_;
    } else {
        size_t wr = (size_t)(e * 512 + nt * 128 + lr) * D_;
        lsrc = (lt == 2 ? g_W1 : g_W0) + wr;
    }
    const uint32_t sb = smem_u32(smem) + 1024;
    const uint32_t sw16 = (uint32_t)((lr >> 2) & 1) * 16;
    const uint32_t dst0 = (uint32_t)lt * 4096 + (uint32_t)lr * 32;

    #define LOAD_STAGE(st, kc) do {                                                  \
        uint32_t d_ = sb + (uint32_t)(st) * STG + dst0;                               \
        const int8_t* s_ = lsrc + (kc) * 32;                                          \
        CP16(d_ + sw16, s_); CP16(d_ + (sw16 ^ 16), s_ + 16);                         \
        asm volatile("cp.async.commit_group;" ::: "memory");                          \
    } while (0)

    // ---- mma fragment addressing ----
    const int m0 = (wid & 3) * 32;
    const int n0 = (wid >> 2) * 32;
    const uint32_t lr8 = lane & 7;
    const uint32_t ls8 = ((lane >> 3) & 1) * 8;
    const uint32_t lc  = (lane >> 4) & 1;
    uint32_t aoff[2], boff[2];
    #pragma unroll
    for (int g = 0; g < 2; g++) {
        uint32_t rA = (uint32_t)m0 + 16u * g + lr8 + ls8;
        aoff[g] = rA * 32 + ((lc ^ ((rA >> 2) & 1)) * 16);
        uint32_t rB = (uint32_t)n0 + 16u * g + lr8 + ls8;
        boff[g] = rB * 32 + ((lc ^ ((rB >> 2) & 1)) * 16);
    }

    int acc1[2][4][4], accx[2][4][4];
    #pragma unroll
    for (int g = 0; g < 2; g++)
        #pragma unroll
        for (int n = 0; n < 4; n++)
            #pragma unroll
            for (int q = 0; q < 4; q++) { acc1[g][n][q] = 0; accx[g][n][q] = 0; }

    LOAD_STAGE(0, 0);
    LOAD_STAGE(1, 1);
    LOAD_STAGE(2, 2);

    for (int kc = 0; kc < 16; kc++) {
        if (kc < 14)       asm volatile("cp.async.wait_group 2;" ::: "memory");
        else if (kc == 14) asm volatile("cp.async.wait_group 1;" ::: "memory");
        else               asm volatile("cp.async.wait_group 0;" ::: "memory");
        __syncthreads();
        if (kc + 3 < 16) LOAD_STAGE((kc + 3) & 3, kc + 3);

        const uint32_t stb = sb + (uint32_t)(kc & 3) * STG;

        uint32_t a1[2][4], a0f[2][4];
        #pragma unroll
        for (int g = 0; g < 2; g++) {
            LDSM4(a1[g],  stb + OFF_A1 + aoff[g]);
            LDSM4(a0f[g], stb + OFF_A0 + aoff[g]);
        }
        #pragma unroll
        for (int h = 0; h < 2; h++) {
            uint32_t w1[4], w0[4];
            LDSM4(w1, stb + OFF_W1 + boff[h]);
            LDSM4(w0, stb + OFF_W0 + boff[h]);
            #pragma unroll
            for (int g = 0; g < 2; g++) {
                #pragma unroll
                for (int j = 0; j < 2; j++) {
                    int* c1 = acc1[g][2 * h + j];
                    int* cx = accx[g][2 * h + j];
                    IMMA(c1, a1[g],  w1[j], w1[2 + j]);
                    IMMA(cx, a1[g],  w0[j], w0[2 + j]);
                    IMMA(cx, a0f[g], w1[j], w1[2 + j]);
                }
            }
        }
    }

    // ---- epilogue: combine limbs, scale, bias, scatter ----
    const int grp = lane >> 2, q = lane & 3;
    #pragma unroll
    for (int g = 0; g < 2; g++) {
        const int r0 = m0 + 16 * g + grp;
        const int tok0 = rows[r0], tok1 = rows[r0 + 8];
        const float sx0 = (tok0 >= 0) ? g_sx[tok0] : 0.f;
        const float sx1 = (tok1 >= 0) ? g_sx[tok1] : 0.f;
        #pragma unroll
        for (int ng = 0; ng < 4; ng++) {
            const int col = nt * 128 + n0 + (ng >> 1) * 16 + (ng & 1) * 8 + 2 * q;
            const float2 swv = *(const float2*)(g_sw + e * D_ + col);
            const float2 bv  = *(const float2*)(bias + e * D_ + col);
            const int* c1 = acc1[g][ng];
            const int* cx = accx[g][ng];
            if (tok0 >= 0) {
                float v0 = 65536.f * (float)c1[0] + 256.f * (float)cx[0];
                float v1 = 65536.f * (float)c1[1] + 256.f * (float)cx[1];
                float2 o = make_float2(sx0 * swv.x * v0 + bv.x,
                                       sx0 * swv.y * v1 + bv.y);
                *(float2*)(out + (size_t)tok0 * D_ + col) = o;
            }
            if (tok1 >= 0) {
                float v2 = 65536.f * (float)c1[2] + 256.f * (float)cx[2];
                float v3 = 65536.f * (float)c1[3] + 256.f * (float)cx[3];
                float2 o = make_float2(sx1 * swv.x * v2 + bv.x,
                                       sx1 * swv.y * v3 + bv.y);
                *(float2*)(out + (size_t)tok1 * D_ + col) = o;
            }
        }
    }
}

// ---------------- launch ----------------
extern "C" void kernel_launch(void* const* d_in, const int* in_sizes, int n_in,
                              void* d_out, int out_size) {
    const float* x = (const float*)d_in[0];
    const int*   p = (const int*)d_in[1];
    const float* W = (const float*)d_in[2];
    const float* b = (const float*)d_in[3];
    float* out = (float*)d_out;
    const int T = in_sizes[1];

    static bool attr_done = false;
    if (!attr_done) {
        cudaFuncSetAttribute(k_gemm, cudaFuncAttributeMaxDynamicSharedMemorySize, SMEM_GEMM);
        attr_done = true;
    }

    k_zero<<<1, 32>>>();
    k_count<<<(T + 255) / 256, 256>>>(p, T);
    k_prefix<<<1, 1>>>();
    k_scatter<<<(T + 255) / 256, 256>>>(p, T);
    k_quant_x<<<TMAX / 8, 256>>>(x);
    k_quant_w<<<(E_ * D_) / 8, 256>>>(W);

    dim3 grid(4, MAXTILES, 1);
    k_gemm<<<grid, 512, SMEM_GEMM>>>(b, out);
}

// round 6
// speedup vs baseline: 4.1431x; 4.1431x over previous
#include <cuda_runtime.h>
#include <cuda_fp16.h>
#include <cstdint>

#define E_      8
#define D_      512
#define TMAX    32768
#define MAXTILES 264

// ---------------- scratch (allocation-free __device__ globals) ----------------
__device__ int g_counts[E_];
__device__ int g_offsets[E_];
__device__ int g_cursor[E_];
__device__ int g_bucket[TMAX];
__device__ int g_tile_e[MAXTILES];
__device__ int g_tile_m[MAXTILES];
__device__ int g_num_tiles;

__device__ __align__(16) __half g_Xh[(size_t)TMAX * D_];
__device__ __align__(16) __half g_Wh[(size_t)E_ * D_ * D_];

// ---------------- helpers ----------------
__device__ __forceinline__ uint32_t smem_u32(const void* p) {
    uint32_t a;
    asm("{ .reg .u64 t; cvta.to.shared.u64 t, %1; cvt.u32.u64 %0, t; }" : "=r"(a) : "l"(p));
    return a;
}

#define CP16(d, s) asm volatile("cp.async.cg.shared.global [%0], [%1], 16;" :: "r"(d), "l"(s) : "memory")

#define LDSM4(r, a)                                                                  \
    asm volatile("ldmatrix.sync.aligned.m8n8.x4.shared.b16 {%0,%1,%2,%3}, [%4];"     \
        : "=r"((r)[0]), "=r"((r)[1]), "=r"((r)[2]), "=r"((r)[3]) : "r"(a))

#define MMA(c, a, b)                                                                 \
    asm volatile("mma.sync.aligned.m16n8k16.row.col.f32.f16.f16.f32 "                \
        "{%0,%1,%2,%3},{%4,%5,%6,%7},{%8,%9},{%0,%1,%2,%3};"                         \
        : "+f"((c)[0]), "+f"((c)[1]), "+f"((c)[2]), "+f"((c)[3])                     \
        : "r"((a)[0]), "r"((a)[1]), "r"((a)[2]), "r"((a)[3]),                        \
          "r"((b)[0]), "r"((b)[1]))

// ---------------- bucketing ----------------
__global__ void k_zero() {
    int i = threadIdx.x;
    if (i < E_) { g_counts[i] = 0; g_cursor[i] = 0; }
}

__global__ void k_count(const int* __restrict__ p, int T) {
    __shared__ int s[E_];
    if (threadIdx.x < E_) s[threadIdx.x] = 0;
    __syncthreads();
    int t = blockIdx.x * blockDim.x + threadIdx.x;
    if (t < T) atomicAdd(&s[p[t]], 1);
    __syncthreads();
    if (threadIdx.x < E_ && s[threadIdx.x]) atomicAdd(&g_counts[threadIdx.x], s[threadIdx.x]);
}

__global__ void k_prefix() {
    if (threadIdx.x == 0) {
        int acc = 0;
        for (int e = 0; e < E_; e++) { g_offsets[e] = acc; acc += g_counts[e]; }
        int nt = 0;
        for (int e = 0; e < E_; e++) {
            int mt = (g_counts[e] + 127) >> 7;
            for (int m = 0; m < mt; m++) { g_tile_e[nt] = e; g_tile_m[nt] = m; nt++; }
        }
        g_num_tiles = nt;
    }
}

__global__ void k_scatter(const int* __restrict__ p, int T) {
    __shared__ int s_cnt[E_], s_base[E_];
    if (threadIdx.x < E_) s_cnt[threadIdx.x] = 0;
    __syncthreads();
    int t = blockIdx.x * blockDim.x + threadIdx.x;
    int e = 0, rank = 0;
    if (t < T) { e = p[t]; rank = atomicAdd(&s_cnt[e], 1); }
    __syncthreads();
    if (threadIdx.x < E_ && s_cnt[threadIdx.x])
        s_base[threadIdx.x] = atomicAdd(&g_cursor[threadIdx.x], s_cnt[threadIdx.x]);
    __syncthreads();
    if (t < T) g_bucket[g_offsets[e] + s_base[e] + rank] = t;
}

// ---------------- fp32 -> fp16 convert ----------------
__global__ void k_convx(const float* __restrict__ x) {
    size_t i = (size_t)blockIdx.x * blockDim.x + threadIdx.x;   // per 8 floats
    float4 v0 = ((const float4*)x)[2 * i];
    float4 v1 = ((const float4*)x)[2 * i + 1];
    __half2 h0 = __floats2half2_rn(v0.x, v0.y);
    __half2 h1 = __floats2half2_rn(v0.z, v0.w);
    __half2 h2 = __floats2half2_rn(v1.x, v1.y);
    __half2 h3 = __floats2half2_rn(v1.z, v1.w);
    uint4 o;
    o.x = *(uint32_t*)&h0; o.y = *(uint32_t*)&h1;
    o.z = *(uint32_t*)&h2; o.w = *(uint32_t*)&h3;
    ((uint4*)g_Xh)[i] = o;
}

__global__ void k_convw(const float* __restrict__ W) {
    size_t i = (size_t)blockIdx.x * blockDim.x + threadIdx.x;   // per 8 floats
    float4 v0 = ((const float4*)W)[2 * i];
    float4 v1 = ((const float4*)W)[2 * i + 1];
    __half2 h0 = __floats2half2_rn(v0.x, v0.y);
    __half2 h1 = __floats2half2_rn(v0.z, v0.w);
    __half2 h2 = __floats2half2_rn(v1.x, v1.y);
    __half2 h3 = __floats2half2_rn(v1.z, v1.w);
    uint4 o;
    o.x = *(uint32_t*)&h0; o.y = *(uint32_t*)&h1;
    o.z = *(uint32_t*)&h2; o.w = *(uint32_t*)&h3;
    ((uint4*)g_Wh)[i] = o;
}

// ---------------- grouped GEMM: single-pass FP16 HMMA ----------------
// CTA 128(M) x 128(N), K=512 in 16 chunks of 32. 8 warps, warp tile 32x64.
// SMEM tile: 128 rows x 64B, XOR swizzle on 16B chunks: c' = c ^ ((row>>1)&3).
#define OFF_A       0
#define OFF_W       8192
#define STG         16384
#define NST         4
#define SMEM_GEMM   (1024 + NST * STG)

__global__ void __launch_bounds__(256, 2)
k_gemm(const float* __restrict__ bias, float* __restrict__ out) {
    extern __shared__ unsigned char smem[];
    const int ti = blockIdx.y;
    if (ti >= g_num_tiles) return;
    const int nt    = blockIdx.x;
    const int e     = g_tile_e[ti];
    const int mtile = g_tile_m[ti];
    const int count = g_counts[e];
    const int base  = g_offsets[e];

    int* rows = (int*)smem;
    const int tid = threadIdx.x, lane = tid & 31, wid = tid >> 5;

    if (tid < 128) {
        int m = mtile * 128 + tid;
        rows[tid] = (m < count) ? g_bucket[base + m] : -1;
    }
    __syncthreads();

    // ---- loader setup: thread -> row = tid>>1, 32B half = tid&1 ----
    const int lrow = tid >> 1;
    const uint32_t c0 = (uint32_t)(tid & 1) * 2;           // 16B chunk index 0 or 2
    const uint32_t lsw = (uint32_t)((lrow >> 1) & 3);      // swizzle xor
    const uint32_t d0 = ((c0 ^ lsw) * 16);                 // swizzled chunk byte
    int tokA = rows[lrow]; if (tokA < 0) tokA = 0;
    const char* srcA = (const char*)(g_Xh + (size_t)tokA * D_) + c0 * 16;
    const size_t wrow = ((size_t)e * D_ + (size_t)(nt * 128 + lrow)) * D_;
    const char* srcW = (const char*)(g_Wh + wrow) + c0 * 16;

    const uint32_t sb = smem_u32(smem) + 1024;
    const uint32_t dbase = (uint32_t)lrow * 64;

    // ---- mma fragment addressing ----
    const int m0 = (wid & 3) * 32;
    const int n0 = (wid >> 2) * 64;
    const uint32_t rA  = (uint32_t)(m0 + (lane & 15));
    const uint32_t hA  = (uint32_t)((lane >> 4) & 1);
    const uint32_t sA  = (rA >> 1) & 3;
    const uint32_t rowA = rA * 64;
    const uint32_t rB0 = (uint32_t)(n0 + ((lane >> 4) & 1) * 8 + (lane & 7));
    const uint32_t hB  = (uint32_t)((lane >> 3) & 1);
    const uint32_t sB  = (rB0 >> 1) & 3;
    const uint32_t rowB = rB0 * 64;

    float acc[2][8][4];
    #pragma unroll
    for (int i = 0; i < 2; i++)
        #pragma unroll
        for (int j = 0; j < 8; j++)
            #pragma unroll
            for (int q = 0; q < 4; q++) acc[i][j][q] = 0.f;

    #define LOAD_STAGE(st, kc) do {                                                  \
        uint32_t b_ = sb + (uint32_t)(st) * STG + dbase + d0;                         \
        size_t g_ = (size_t)(kc) * 64;                                                \
        CP16(b_ + OFF_A, srcA + g_); CP16((b_ + OFF_A) ^ 16, srcA + g_ + 16);         \
        CP16(b_ + OFF_W, srcW + g_); CP16((b_ + OFF_W) ^ 16, srcW + g_ + 16);         \
        asm volatile("cp.async.commit_group;" ::: "memory");                          \
    } while (0)

    LOAD_STAGE(0, 0);
    LOAD_STAGE(1, 1);
    LOAD_STAGE(2, 2);

    for (int kc = 0; kc < 16; kc++) {
        if (kc < 14)       asm volatile("cp.async.wait_group 2;" ::: "memory");
        else if (kc == 14) asm volatile("cp.async.wait_group 1;" ::: "memory");
        else               asm volatile("cp.async.wait_group 0;" ::: "memory");
        __syncthreads();
        if (kc + 3 < 16) LOAD_STAGE((kc + 3) & 3, kc + 3);

        const uint32_t stb = sb + (uint32_t)(kc & 3) * STG;

        #pragma unroll
        for (int ks = 0; ks < 2; ks++) {
            const uint32_t ca = (((uint32_t)(2 * ks) + hA) ^ sA) * 16;
            const uint32_t cb = (((uint32_t)(2 * ks) + hB) ^ sB) * 16;
            uint32_t a0[4], a1[4];
            LDSM4(a0, stb + OFF_A + rowA + ca);
            LDSM4(a1, stb + OFF_A + rowA + 1024 + ca);

            #pragma unroll
            for (int pp = 0; pp < 4; pp++) {
                const uint32_t rb = rowB + (uint32_t)pp * 1024;
                uint32_t bw[4];
                LDSM4(bw, stb + OFF_W + rb + cb);
                MMA(acc[0][2 * pp],     a0, (bw + 0));
                MMA(acc[1][2 * pp],     a1, (bw + 0));
                MMA(acc[0][2 * pp + 1], a0, (bw + 2));
                MMA(acc[1][2 * pp + 1], a1, (bw + 2));
            }
        }
    }

    // ---- epilogue: bias + scatter by token ----
    const int gid = lane >> 2, tig = lane & 3;
    const int ncol0 = nt * 128 + n0 + 2 * tig;
    float2 bv[8];
    #pragma unroll
    for (int nb = 0; nb < 8; nb++)
        bv[nb] = *(const float2*)(bias + e * D_ + ncol0 + nb * 8);

    #pragma unroll
    for (int mf = 0; mf < 2; mf++) {
        #pragma unroll
        for (int h = 0; h < 2; h++) {
            int m = m0 + mf * 16 + h * 8 + gid;
            int tok = rows[m];
            if (tok < 0) continue;
            float* orow = out + (size_t)tok * D_ + ncol0;
            #pragma unroll
            for (int nb = 0; nb < 8; nb++) {
                float2 o;
                o.x = acc[mf][nb][2 * h]     + bv[nb].x;
                o.y = acc[mf][nb][2 * h + 1] + bv[nb].y;
                *(float2*)(orow + nb * 8) = o;
            }
        }
    }
}

// ---------------- launch ----------------
extern "C" void kernel_launch(void* const* d_in, const int* in_sizes, int n_in,
                              void* d_out, int out_size) {
    const float* x = (const float*)d_in[0];
    const int*   p = (const int*)d_in[1];
    const float* W = (const float*)d_in[2];
    const float* b = (const float*)d_in[3];
    float* out = (float*)d_out;
    const int T = in_sizes[1];

    static bool attr_done = false;
    if (!attr_done) {
        cudaFuncSetAttribute(k_gemm, cudaFuncAttributeMaxDynamicSharedMemorySize, SMEM_GEMM);
        attr_done = true;
    }

    k_zero<<<1, 32>>>();
    k_count<<<(T + 255) / 256, 256>>>(p, T);
    k_prefix<<<1, 1>>>();
    k_scatter<<<(T + 255) / 256, 256>>>(p, T);
    k_convx<<<(TMAX * D_ / 8) / 256, 256>>>(x);
    k_convw<<<(E_ * D_ * D_ / 8) / 256, 256>>>(W);

    dim3 grid(4, MAXTILES, 1);
    k_gemm<<<grid, 256, SMEM_GEMM>>>(b, out);
}

// round 7
// speedup vs baseline: 4.2152x; 1.0174x over previous
#include <cuda_runtime.h>
#include <cuda_fp16.h>
#include <cstdint>

#define E_      8
#define D_      512
#define TMAX    32768
#define MAXTILES 264

// ---------------- scratch (allocation-free __device__ globals) ----------------
__device__ int g_cursor[E_];
__device__ int g_counts[E_];
__device__ int g_bucket[E_ * TMAX];          // per-expert fixed-capacity buckets
__device__ int g_tile_e[MAXTILES];
__device__ int g_tile_m[MAXTILES];
__device__ int g_num_tiles;

__device__ __align__(16) __half g_Wh[(size_t)E_ * D_ * D_];

// ---------------- helpers ----------------
__device__ __forceinline__ uint32_t smem_u32(const void* p) {
    uint32_t a;
    asm("{ .reg .u64 t; cvta.to.shared.u64 t, %1; cvt.u32.u64 %0, t; }" : "=r"(a) : "l"(p));
    return a;
}

#define CP16(d, s) asm volatile("cp.async.cg.shared.global [%0], [%1], 16;" :: "r"(d), "l"(s) : "memory")

#define LDSM4(r, a)                                                                  \
    asm volatile("ldmatrix.sync.aligned.m8n8.x4.shared.b16 {%0,%1,%2,%3}, [%4];"     \
        : "=r"((r)[0]), "=r"((r)[1]), "=r"((r)[2]), "=r"((r)[3]) : "r"(a))

#define MMA(c, a, b)                                                                 \
    asm volatile("mma.sync.aligned.m16n8k16.row.col.f32.f16.f16.f32 "                \
        "{%0,%1,%2,%3},{%4,%5,%6,%7},{%8,%9},{%0,%1,%2,%3};"                         \
        : "+f"((c)[0]), "+f"((c)[1]), "+f"((c)[2]), "+f"((c)[3])                     \
        : "r"((a)[0]), "r"((a)[1]), "r"((a)[2]), "r"((a)[3]),                        \
          "r"((b)[0]), "r"((b)[1]))

// ---------------- prep: convert W to fp16 + zero cursors ----------------
__global__ void k_prep(const float* __restrict__ W) {
    if (blockIdx.x == 0 && threadIdx.x < E_) g_cursor[threadIdx.x] = 0;
    size_t i = (size_t)blockIdx.x * blockDim.x + threadIdx.x;   // per 8 floats
    float4 v0 = ((const float4*)W)[2 * i];
    float4 v1 = ((const float4*)W)[2 * i + 1];
    __half2 h0 = __floats2half2_rn(v0.x, v0.y);
    __half2 h1 = __floats2half2_rn(v0.z, v0.w);
    __half2 h2 = __floats2half2_rn(v1.x, v1.y);
    __half2 h3 = __floats2half2_rn(v1.z, v1.w);
    uint4 o;
    o.x = *(uint32_t*)&h0; o.y = *(uint32_t*)&h1;
    o.z = *(uint32_t*)&h2; o.w = *(uint32_t*)&h3;
    ((uint4*)g_Wh)[i] = o;
}

// ---------------- direct scatter into per-expert buckets ----------------
__global__ void k_scat(const int* __restrict__ p, int T) {
    __shared__ int s_cnt[E_], s_base[E_];
    if (threadIdx.x < E_) s_cnt[threadIdx.x] = 0;
    __syncthreads();
    int t = blockIdx.x * blockDim.x + threadIdx.x;
    int e = 0, rank = 0;
    if (t < T) { e = p[t]; rank = atomicAdd(&s_cnt[e], 1); }
    __syncthreads();
    if (threadIdx.x < E_ && s_cnt[threadIdx.x])
        s_base[threadIdx.x] = atomicAdd(&g_cursor[threadIdx.x], s_cnt[threadIdx.x]);
    __syncthreads();
    if (t < T) g_bucket[e * TMAX + s_base[e] + rank] = t;
}

// ---------------- tile list ----------------
__global__ void k_tiles() {
    if (threadIdx.x == 0) {
        int nt = 0;
        for (int e = 0; e < E_; e++) {
            int c = g_cursor[e];
            g_counts[e] = c;
            int mt = (c + 127) >> 7;
            for (int m = 0; m < mt; m++) { g_tile_e[nt] = e; g_tile_m[nt] = m; nt++; }
        }
        g_num_tiles = nt;
    }
}

// ---------------- grouped GEMM: FP16 HMMA, fused x-conversion ----------------
// CTA 128(M) x 128(N), K=512 in 16 chunks of 32. 8 warps, warp tile 32x64.
// SMEM tile: 128 rows x 64B fp16, XOR swizzle on 16B chunks: c' = c ^ ((row>>1)&3).
// A: fp32 gathered LDG (prefetch 1 kc ahead) -> cvt -> STS 2 stages ahead.
// W: cp.async fp16, 3 stages ahead. 4-stage ring.
#define OFF_A       0
#define OFF_W       8192
#define STG         16384
#define NST         4
#define SMEM_GEMM   (1024 + NST * STG)

__global__ void __launch_bounds__(256, 2)
k_gemm(const float* __restrict__ x, const float* __restrict__ bias,
       float* __restrict__ out) {
    extern __shared__ unsigned char smem[];
    const int ti = blockIdx.y;
    if (ti >= g_num_tiles) return;
    const int nt    = blockIdx.x;
    const int e     = g_tile_e[ti];
    const int mtile = g_tile_m[ti];
    const int count = g_counts[e];

    int* rows = (int*)smem;
    const int tid = threadIdx.x, lane = tid & 31, wid = tid >> 5;

    if (tid < 128) {
        int m = mtile * 128 + tid;
        rows[tid] = (m < count) ? g_bucket[e * TMAX + m] : -1;
    }
    __syncthreads();

    // ---- loader setup: thread -> row = tid>>1, 64B fp32 half = tid&1 ----
    const int lrow = tid >> 1;
    const int hh = tid & 1;
    int tokA = rows[lrow]; if (tokA < 0) tokA = 0;
    const float4* srcA32 = (const float4*)(x + (size_t)tokA * D_) + hh * 4;
    const char* srcW = (const char*)(g_Wh + ((size_t)e * D_ + (size_t)(nt * 128 + lrow)) * D_)
                       + hh * 32;

    const uint32_t sb = smem_u32(smem) + 1024;
    const uint32_t c0 = (uint32_t)hh * 2;
    const uint32_t sw_ = (uint32_t)((lrow >> 1) & 3);
    const uint32_t dA0 = (uint32_t)lrow * 64 + ((c0 ^ sw_) * 16);   // also W dst

    // ---- mma fragment addressing ----
    const int m0 = (wid & 3) * 32;
    const int n0 = (wid >> 2) * 64;
    const uint32_t rA  = (uint32_t)(m0 + (lane & 15));
    const uint32_t hA  = (uint32_t)((lane >> 4) & 1);
    const uint32_t sA  = (rA >> 1) & 3;
    const uint32_t rowA = rA * 64;
    const uint32_t rB0 = (uint32_t)(n0 + ((lane >> 4) & 1) * 8 + (lane & 7));
    const uint32_t hB  = (uint32_t)((lane >> 3) & 1);
    const uint32_t sB  = (rB0 >> 1) & 3;
    const uint32_t rowB = rB0 * 64;

    float acc[2][8][4];
    #pragma unroll
    for (int i = 0; i < 2; i++)
        #pragma unroll
        for (int j = 0; j < 8; j++)
            #pragma unroll
            for (int q = 0; q < 4; q++) acc[i][j][q] = 0.f;

    #define W_STAGE(st, kc) do {                                                     \
        uint32_t d_ = sb + (uint32_t)(st) * STG + OFF_W + dA0;                        \
        const char* s_ = srcW + (size_t)(kc) * 64;                                    \
        CP16(d_, s_); CP16(d_ ^ 16, s_ + 16);                                         \
        asm volatile("cp.async.commit_group;" ::: "memory");                          \
    } while (0)

    #define A_STORE(st, t4) do {                                                     \
        uint32_t r_[8];                                                              \
        _Pragma("unroll")                                                            \
        for (int j = 0; j < 4; j++) {                                                \
            __half2 p0 = __floats2half2_rn((t4)[j].x, (t4)[j].y);                     \
            __half2 p1 = __floats2half2_rn((t4)[j].z, (t4)[j].w);                     \
            r_[2 * j] = *(uint32_t*)&p0; r_[2 * j + 1] = *(uint32_t*)&p1;             \
        }                                                                            \
        uint32_t d_ = sb + (uint32_t)(st) * STG + OFF_A + dA0;                        \
        *(uint4*)(smem + (d_ - smem_u32(smem)))                                       \
            = make_uint4(r_[0], r_[1], r_[2], r_[3]);                                 \
        *(uint4*)(smem + ((d_ ^ 16) - smem_u32(smem)))                                \
            = make_uint4(r_[4], r_[5], r_[6], r_[7]);                                 \
    } while (0)

    // prologue: A stages 0,1 direct; prefetch A(2); W stages 0,1,2 async
    float4 aPre[4];
    {
        float4 t4[4];
        #pragma unroll
        for (int s = 0; s < 2; s++) {
            #pragma unroll
            for (int j = 0; j < 4; j++) t4[j] = srcA32[s * 8 + j];
            A_STORE(s, t4);
        }
        #pragma unroll
        for (int j = 0; j < 4; j++) aPre[j] = srcA32[16 + j];
    }
    W_STAGE(0, 0);
    W_STAGE(1, 1);
    W_STAGE(2, 2);

    for (int kc = 0; kc < 16; kc++) {
        if (kc < 14)       asm volatile("cp.async.wait_group 2;" ::: "memory");
        else if (kc == 14) asm volatile("cp.async.wait_group 1;" ::: "memory");
        else               asm volatile("cp.async.wait_group 0;" ::: "memory");
        __syncthreads();

        if (kc + 3 < 16) W_STAGE((kc + 3) & 3, kc + 3);
        if (kc + 2 < 16) A_STORE((kc + 2) & 3, aPre);
        if (kc + 3 < 16) {
            #pragma unroll
            for (int j = 0; j < 4; j++) aPre[j] = srcA32[(kc + 3) * 8 + j];
        }

        const uint32_t stb = sb + (uint32_t)(kc & 3) * STG;

        #pragma unroll
        for (int ks = 0; ks < 2; ks++) {
            const uint32_t ca = (((uint32_t)(2 * ks) + hA) ^ sA) * 16;
            const uint32_t cb = (((uint32_t)(2 * ks) + hB) ^ sB) * 16;
            uint32_t a0[4], a1[4];
            LDSM4(a0, stb + OFF_A + rowA + ca);
            LDSM4(a1, stb + OFF_A + rowA + 1024 + ca);

            #pragma unroll
            for (int pp = 0; pp < 4; pp++) {
                const uint32_t rb = rowB + (uint32_t)pp * 1024;
                uint32_t bw[4];
                LDSM4(bw, stb + OFF_W + rb + cb);
                MMA(acc[0][2 * pp],     a0, (bw + 0));
                MMA(acc[1][2 * pp],     a1, (bw + 0));
                MMA(acc[0][2 * pp + 1], a0, (bw + 2));
                MMA(acc[1][2 * pp + 1], a1, (bw + 2));
            }
        }
    }

    // ---- epilogue: bias + scatter by token ----
    const int gid = lane >> 2, tig = lane & 3;
    const int ncol0 = nt * 128 + n0 + 2 * tig;
    float2 bv[8];
    #pragma unroll
    for (int nb = 0; nb < 8; nb++)
        bv[nb] = *(const float2*)(bias + e * D_ + ncol0 + nb * 8);

    #pragma unroll
    for (int mf = 0; mf < 2; mf++) {
        #pragma unroll
        for (int h = 0; h < 2; h++) {
            int m = m0 + mf * 16 + h * 8 + gid;
            int tok = rows[m];
            if (tok < 0) continue;
            float* orow = out + (size_t)tok * D_ + ncol0;
            #pragma unroll
            for (int nb = 0; nb < 8; nb++) {
                float2 o;
                o.x = acc[mf][nb][2 * h]     + bv[nb].x;
                o.y = acc[mf][nb][2 * h + 1] + bv[nb].y;
                *(float2*)(orow + nb * 8) = o;
            }
        }
    }
}

// ---------------- launch ----------------
extern "C" void kernel_launch(void* const* d_in, const int* in_sizes, int n_in,
                              void* d_out, int out_size) {
    const float* x = (const float*)d_in[0];
    const int*   p = (const int*)d_in[1];
    const float* W = (const float*)d_in[2];
    const float* b = (const float*)d_in[3];
    float* out = (float*)d_out;
    const int T = in_sizes[1];

    static bool attr_done = false;
    if (!attr_done) {
        cudaFuncSetAttribute(k_gemm, cudaFuncAttributeMaxDynamicSharedMemorySize, SMEM_GEMM);
        attr_done = true;
    }

    k_prep<<<(E_ * D_ * D_ / 8) / 256, 256>>>(W);
    k_scat<<<(T + 255) / 256, 256>>>(p, T);
    k_tiles<<<1, 32>>>();

    dim3 grid(4, MAXTILES, 1);
    k_gemm<<<grid, 256, SMEM_GEMM>>>(x, b, out);
}